// round 15
// baseline (speedup 1.0000x reference)
#include <cuda_runtime.h>
#include <cuda_bf16.h>
#include <cuda_fp16.h>
#include <cstdint>
#include <math.h>

#define B_ 8
#define C_ 128
#define N_ 32768
#define NEL 4194304
#define MLP_ 512
#define EPS_ 1e-5f
#define SCALE_ 0.25f
#define LDE 136
#define LDH2 72
#define LDXH 68
#define GLD 72
#define LDS_ 133

// ---------------- scratch ----------------
__device__ float         g_G[B_][C_][C_];
__device__ float         g_M[B_][C_][C_];
__device__ float         g_s[B_][C_];
__device__ __nv_bfloat16 g_E[B_][C_][C_];
__device__ float         g_stats[4][B_];
__device__ float         g_norm[4][B_];
__device__ __nv_bfloat16 g_W1[MLP_*C_];
__device__ __nv_bfloat16 g_W2[C_*MLP_];
__device__ __half        g_z [(size_t)B_*NEL];

// ---------------- helpers ----------------
__device__ __forceinline__ uint32_t s2u(const void* p){
    return (uint32_t)__cvta_generic_to_shared(p);
}
__device__ __forceinline__ void ldsmx4(uint32_t* r, uint32_t a){
    asm volatile("ldmatrix.sync.aligned.m8n8.x4.shared.b16 {%0,%1,%2,%3},[%4];"
        : "=r"(r[0]),"=r"(r[1]),"=r"(r[2]),"=r"(r[3]) : "r"(a));
}
__device__ __forceinline__ void ldsmx4t(uint32_t* r, uint32_t a){
    asm volatile("ldmatrix.sync.aligned.m8n8.x4.trans.shared.b16 {%0,%1,%2,%3},[%4];"
        : "=r"(r[0]),"=r"(r[1]),"=r"(r[2]),"=r"(r[3]) : "r"(a));
}
__device__ __forceinline__ void mma_bf16(float* c, const uint32_t* a, const uint32_t* b){
    asm volatile("mma.sync.aligned.m16n8k16.row.col.f32.bf16.bf16.f32 "
        "{%0,%1,%2,%3},{%4,%5,%6,%7},{%8,%9},{%0,%1,%2,%3};"
        : "+f"(c[0]),"+f"(c[1]),"+f"(c[2]),"+f"(c[3])
        : "r"(a[0]),"r"(a[1]),"r"(a[2]),"r"(a[3]),"r"(b[0]),"r"(b[1]));
}
// fast GELU: v * sigmoid(2u), u = sqrt(2/pi)(v + 0.044715 v^3)
// max abs deviation from exact erf-GELU ~3e-4; contribution to z rms ~4e-5.
__device__ __forceinline__ float gelu_f(float v){
    float u = 0.7978845608028654f*v*fmaf(0.044715f, v*v, 1.0f);
    return __fdividef(v, 1.0f + __expf(-2.0f*u));
}

// ---------------- K0 ----------------
__global__ void k_init(const float* __restrict__ w1, const float* __restrict__ w2){
    int i  = blockIdx.x*blockDim.x + threadIdx.x;
    int st = gridDim.x*blockDim.x;
    float* gg = &g_G[0][0][0];
    for(int t=i; t<B_*C_*C_; t+=st) gg[t] = 0.f;
    float* gsv = &g_s[0][0];
    for(int t=i; t<B_*C_; t+=st) gsv[t] = 0.f;
    float* gs = &g_stats[0][0];
    for(int t=i; t<4*B_; t+=st) gs[t] = 0.f;
    for(int t=i; t<MLP_*C_; t+=st) g_W1[t] = __float2bfloat16(w1[t]);
    for(int t=i; t<C_*MLP_; t+=st) g_W2[t] = __float2bfloat16(w2[t]);
}

// ---------------- K1: Gram G = X X^T (+ row sums); 64 splits ---------------
__global__ void __launch_bounds__(256) k_gram(const float* __restrict__ x){
    __shared__ __nv_bfloat16 Xs[C_][GLD];
    int b = blockIdx.y, split = blockIdx.x;
    const float* xb = x + (size_t)b*NEL + split*512;
    int tid = threadIdx.x, lane = tid&31, warp = tid>>5;
    float acc[16][4];
    #pragma unroll
    for(int i=0;i<16;++i){ acc[i][0]=acc[i][1]=acc[i][2]=acc[i][3]=0.f; }
    float racc[8] = {0.f,0.f,0.f,0.f,0.f,0.f,0.f,0.f};
    for(int kc=0; kc<8; ++kc){
        const float* src = xb + kc*64;
        #pragma unroll
        for(int m=0;m<8;++m){
            int idx = tid + m*256;
            int row = idx>>4, c4 = idx&15;
            float4 v = *(const float4*)(src + (size_t)row*N_ + c4*4);
            __nv_bfloat162* d = (__nv_bfloat162*)&Xs[row][c4*4];
            d[0] = __floats2bfloat162_rn(v.x, v.y);
            d[1] = __floats2bfloat162_rn(v.z, v.w);
            racc[m] += v.x+v.y+v.z+v.w;
        }
        __syncthreads();
        int m0 = warp*16;
        #pragma unroll
        for(int ks=0; ks<4; ++ks){
            int k = ks*16;
            uint32_t a[4];
            ldsmx4(a, s2u(&Xs[m0 + (lane&15)][k + ((lane>>4)&1)*8]));
            #pragma unroll
            for(int nt=0; nt<8; ++nt){
                uint32_t Bv[4];
                ldsmx4(Bv, s2u(&Xs[nt*16 + (lane&7) + ((lane>>4)&1)*8][k + ((lane>>3)&1)*8]));
                mma_bf16(acc[nt*2+0], a, Bv);
                mma_bf16(acc[nt*2+1], a, Bv+2);
            }
        }
        __syncthreads();
    }
    float* Gb = &g_G[b][0][0];
    int r0 = warp*16 + (lane>>2);
    #pragma unroll
    for(int nt=0; nt<16; ++nt){
        int c0 = nt*8 + (lane&3)*2;
        atomicAdd(&Gb[(size_t)r0*C_ + c0],       acc[nt][0]);
        atomicAdd(&Gb[(size_t)r0*C_ + c0+1],     acc[nt][1]);
        atomicAdd(&Gb[(size_t)(r0+8)*C_ + c0],   acc[nt][2]);
        atomicAdd(&Gb[(size_t)(r0+8)*C_ + c0+1], acc[nt][3]);
    }
    #pragma unroll
    for(int m=0;m<8;++m){
        #pragma unroll
        for(int o=8;o>0;o>>=1)
            racc[m] += __shfl_xor_sync(0xffffffffu, racc[m], o, 16);
    }
    if((tid&15)==0){
        int rb = tid>>4;
        #pragma unroll
        for(int m=0;m<8;++m)
            atomicAdd(&g_s[b][rb + 16*m], racc[m]);
    }
}

// ---------------- K2a ----------------
__global__ void __launch_bounds__(1024) k_attA(const float* __restrict__ qkv_w){
    extern __shared__ float sa[];
    float* Gs  = sa;
    float* Wq  = Gs + 16384;
    float* Wk  = Wq + 16*LDS_;
    float* Wv  = Wk + 16*LDS_;
    float* Ts  = Wv + 16*LDS_;
    float* As  = Ts + 16*LDS_;
    int h = blockIdx.x, b = blockIdx.y, tid = threadIdx.x;
    int r0 = h*16;
    const float* Gb = &g_G[b][0][0];
    for(int i=tid; i<4096; i+=1024)
        *(float4*)&Gs[i*4] = *(const float4*)&Gb[i*4];
    for(int i=tid; i<2048; i+=1024){
        int r = i>>7, c = i&127;
        Wq[r*LDS_+c] = qkv_w[(size_t)(r0+r)*C_ + c];
        Wk[r*LDS_+c] = qkv_w[(size_t)(C_+r0+r)*C_ + c];
        Wv[r*LDS_+c] = qkv_w[(size_t)(2*C_+r0+r)*C_ + c];
    }
    __syncthreads();
    int il = tid>>6, tg = tid&63;
    {
        float a0 = 0.f, a1 = 0.f;
        #pragma unroll 4
        for(int k=0;k<C_;++k){
            float w = Wq[il*LDS_+k];
            a0 += w*Gs[k*128 + tg];
            a1 += w*Gs[k*128 + tg + 64];
        }
        Ts[il*LDS_ + tg]      = a0;
        Ts[il*LDS_ + tg + 64] = a1;
    }
    __syncthreads();
    if(tid < 256){
        int ir = tid>>4, jg = tid&15;
        float l = 0.f;
        #pragma unroll 4
        for(int t=0;t<C_;++t) l += Ts[ir*LDS_+t]*Wk[jg*LDS_+t];
        l *= SCALE_;
        float mx = l;
        #pragma unroll
        for(int o=8;o>0;o>>=1) mx = fmaxf(mx, __shfl_xor_sync(0xffffffffu, mx, o, 16));
        float e = expf(l-mx), s = e;
        #pragma unroll
        for(int o=8;o>0;o>>=1) s += __shfl_xor_sync(0xffffffffu, s, o, 16);
        As[ir*16+jg] = e/s;
    }
    __syncthreads();
    {
        float a0 = 0.f, a1 = 0.f;
        #pragma unroll
        for(int j=0;j<16;++j){
            float a = As[il*16+j];
            a0 += a*Wv[j*LDS_ + tg];
            a1 += a*Wv[j*LDS_ + tg + 64];
        }
        g_M[b][r0+il][tg]      = a0;
        g_M[b][r0+il][tg + 64] = a1;
    }
}

// ---------------- K2b ----------------
__global__ void __launch_bounds__(1024) k_attB(const float* __restrict__ proj_w,
                                               const float* __restrict__ proj_b){
    extern __shared__ float sb[];
    float* Gs  = sb;
    float* MS  = Gs + 16384;
    float* Wp  = MS + 16384;
    float* Es  = Wp + 16*LDS_;
    float* sv  = Es + 16*LDS_;
    float* red = sv + 128;
    int rg = blockIdx.x, b = blockIdx.y, tid = threadIdx.x;
    int r0 = rg*16;
    const float* Gb = &g_G[b][0][0];
    const float* Mb = &g_M[b][0][0];
    for(int i=tid; i<4096; i+=1024){
        *(float4*)&Gs[i*4] = *(const float4*)&Gb[i*4];
        *(float4*)&MS[i*4] = *(const float4*)&Mb[i*4];
    }
    for(int i=tid; i<2048; i+=1024){
        int r = i>>7, c = i&127;
        Wp[r*LDS_+c] = proj_w[(size_t)(r0+r)*C_ + c];
    }
    if(tid<128) sv[tid] = g_s[b][tid];
    __syncthreads();
    int ol = tid>>6, tg = tid&63;
    {
        float a0 = 0.f, a1 = 0.f;
        #pragma unroll 4
        for(int r=0;r<C_;++r){
            float w = Wp[ol*LDS_+r];
            a0 += w*MS[r*128 + tg];
            a1 += w*MS[r*128 + tg + 64];
        }
        int og = r0 + ol;
        g_E[b][og][tg]      = __float2bfloat16(a0);
        g_E[b][og][tg + 64] = __float2bfloat16(a1);
        Es[ol*LDS_ + tg]      = a0 + ((og==tg)      ? 1.f : 0.f);
        Es[ol*LDS_ + tg + 64] = a1 + ((og==tg+64)   ? 1.f : 0.f);
    }
    __syncthreads();
    {
        float q = 0.f, ms = 0.f;
        #pragma unroll
        for(int tt=0;tt<2;++tt){
            int j = tg + tt*64;
            float p = 0.f;
            #pragma unroll 4
            for(int i=0;i<C_;++i) p += Es[ol*LDS_+i]*Gs[i*128 + j];
            float rj = Es[ol*LDS_+j];
            q  += p*rj;
            ms += rj*sv[j];
        }
        #pragma unroll
        for(int o=16;o>0;o>>=1){
            q  += __shfl_xor_sync(0xffffffffu, q,  o);
            ms += __shfl_xor_sync(0xffffffffu, ms, o);
        }
        int wh = (tid>>5)&1;
        if((tid&31)==0){
            red[ol*2 + wh]      = q;
            red[32 + ol*2 + wh] = ms;
        }
    }
    __syncthreads();
    if(tid < 16){
        float q  = red[tid*2] + red[tid*2+1];
        float ms = red[32+tid*2] + red[32+tid*2+1];
        float pb = proj_b[r0+tid];
        float qf = q + 2.f*pb*ms + (float)N_*pb*pb;
        float sf = ms + (float)N_*pb;
        #pragma unroll
        for(int o=8;o>0;o>>=1){
            qf += __shfl_xor_sync(0xffffu, qf, o, 16);
            sf += __shfl_xor_sync(0xffffu, sf, o, 16);
        }
        if(tid==0){
            atomicAdd(&g_stats[1][b], qf);
            atomicAdd(&g_stats[0][b], sf);
        }
    }
}

// ---------------- K5/K7 ----------------
__global__ void k_norm(int stage){
    int b = threadIdx.x;
    if(b < B_){
        float s = g_stats[stage*2][b], q = g_stats[stage*2+1][b];
        float mu = s / (float)NEL;
        float var = q / (float)NEL - mu*mu;
        g_norm[stage*2][b]   = mu;
        g_norm[stage*2+1][b] = rsqrtf(var + EPS_);
    }
}

// ---------------- K6: fused apply + LN1 + MLP ------------------------------
// 64-wide tile, 512 thr, 91KB smem -> 2 CTAs/SM; x1 residual fp16;
// GEMM2 W2 fragments straight from gmem (no staging, 4 barriers total).
__global__ void __launch_bounds__(512,2) k_am(const float* __restrict__ x,
                                              const float* __restrict__ proj_b,
                                              const float* __restrict__ ln1w,
                                              const float* __restrict__ ln1b,
                                              const float* __restrict__ b1,
                                              const float* __restrict__ b2){
    extern __shared__ char smraw[];
    __nv_bfloat16* Hs  = (__nv_bfloat16*)smraw;                    // 512*72*2 = 73728 (Es first)
    __half*        X1h = (__half*)(smraw + 73728);                 // 128*68*2 = 17408
    __nv_bfloat16* Xs  = (__nv_bfloat16*)(smraw + 73728 + 17408);  // 128*72*2 = 18432
    __nv_bfloat16* Es  = Hs;
    int b = blockIdx.x, n0 = blockIdx.y*64;
    int tid = threadIdx.x, lane = tid&31, warp = tid>>5;   // 16 warps
    const float* xb = x + (size_t)b*NEL + n0;
    // stage E (128x128 bf16) and x tile (128x64 bf16)
    #pragma unroll
    for(int m=0;m<4;++m){
        int idx = tid + m*512;
        int r = idx>>4, c8 = (idx&15)*8;
        *(uint4*)&Es[r*LDE + c8] = *(const uint4*)&g_E[b][r][c8];
    }
    #pragma unroll
    for(int m=0;m<4;++m){
        int idx = tid + m*512;
        int r = idx>>4, c4 = (idx&15)*4;
        float4 v = *(const float4*)(xb + (size_t)r*N_ + c4);
        __nv_bfloat162* d = (__nv_bfloat162*)&Xs[r*LDH2 + c4];
        d[0] = __floats2bfloat162_rn(v.x, v.y);
        d[1] = __floats2bfloat162_rn(v.z, v.w);
    }
    __syncthreads();
    int ar = lane>>2, ac = (lane&3)*2;
    float mu1 = g_norm[0][b], rs1 = g_norm[1][b];
    // ---- phase A: two 16x16 tiles per warp
    float xv[2][2][4];
    #pragma unroll
    for(int t=0;t<2;++t){
        int w2 = warp + t*16;
        int m0 = (w2&7)*16, n = (w2>>3)*16;
        int r0 = m0 + ar;
        uint32_t A8[8][4];
        #pragma unroll
        for(int ks=0; ks<8; ++ks)
            ldsmx4(A8[ks], s2u(&Es[(m0 + (lane&15))*LDE + ks*16 + ((lane>>4)&1)*8]));
        float acc[2][4] = {};
        #pragma unroll
        for(int ks=0; ks<8; ++ks){
            uint32_t Bv[4];
            ldsmx4t(Bv, s2u(&Xs[(ks*16 + (lane&7) + ((lane>>3)&1)*8)*LDH2 + n + ((lane>>4)&1)*8]));
            mma_bf16(acc[0], A8[ks], Bv);
            mma_bf16(acc[1], A8[ks], Bv+2);
        }
        float pb0 = proj_b[r0], pb1 = proj_b[r0+8];
        #pragma unroll
        for(int nh=0; nh<2; ++nh){
            int cc = n + nh*8 + ac;
            float2 x0  = *(const float2*)(xb + (size_t)r0*N_ + cc);
            float2 x1v = *(const float2*)(xb + (size_t)(r0+8)*N_ + cc);
            float y00 = x0.x  + acc[nh][0] + pb0;
            float y01 = x0.y  + acc[nh][1] + pb0;
            float y10 = x1v.x + acc[nh][2] + pb1;
            float y11 = x1v.y + acc[nh][3] + pb1;
            float2 w0 = *(const float2*)(ln1w + (size_t)r0*N_ + n0 + cc);
            float2 w1 = *(const float2*)(ln1w + (size_t)(r0+8)*N_ + n0 + cc);
            float2 g0 = *(const float2*)(ln1b + (size_t)r0*N_ + n0 + cc);
            float2 g1 = *(const float2*)(ln1b + (size_t)(r0+8)*N_ + n0 + cc);
            xv[t][nh][0] = (y00-mu1)*rs1*w0.x + g0.x;
            xv[t][nh][1] = (y01-mu1)*rs1*w0.y + g0.y;
            xv[t][nh][2] = (y10-mu1)*rs1*w1.x + g1.x;
            xv[t][nh][3] = (y11-mu1)*rs1*w1.y + g1.y;
        }
    }
    __syncthreads();
    // ---- phase B: store x1 (fp16 residual + bf16 mma input)
    #pragma unroll
    for(int t=0;t<2;++t){
        int w2 = warp + t*16;
        int m0 = (w2&7)*16, n = (w2>>3)*16;
        int r0 = m0 + ar;
        #pragma unroll
        for(int nh=0; nh<2; ++nh){
            int cc = n + nh*8 + ac;
            *(__half2*)&X1h[r0*LDXH + cc]     = __floats2half2_rn(xv[t][nh][0], xv[t][nh][1]);
            *(__half2*)&X1h[(r0+8)*LDXH + cc] = __floats2half2_rn(xv[t][nh][2], xv[t][nh][3]);
            *(__nv_bfloat162*)&Xs[r0*LDH2 + cc]     = __floats2bfloat162_rn(xv[t][nh][0], xv[t][nh][1]);
            *(__nv_bfloat162*)&Xs[(r0+8)*LDH2 + cc] = __floats2bfloat162_rn(xv[t][nh][2], xv[t][nh][3]);
        }
    }
    __syncthreads();
    // ---- GEMM1: hid = gelu(W1 x1 + b1): 16 warps x 2 groups of 16 rows
    #pragma unroll
    for(int g=0; g<2; ++g){
        int ch0 = warp*16 + g*256;
        uint32_t Wf[8][4];
        const __nv_bfloat16* w1p = g_W1 + (size_t)ch0*C_;
        #pragma unroll
        for(int ks=0;ks<8;++ks){
            const __nv_bfloat16* wp = w1p + ks*16;
            Wf[ks][0] = *(const uint32_t*)(wp + (size_t)(ar  )*C_ + ac);
            Wf[ks][1] = *(const uint32_t*)(wp + (size_t)(ar+8)*C_ + ac);
            Wf[ks][2] = *(const uint32_t*)(wp + (size_t)(ar  )*C_ + ac + 8);
            Wf[ks][3] = *(const uint32_t*)(wp + (size_t)(ar+8)*C_ + ac + 8);
        }
        float bb0 = b1[ch0 + ar], bb1 = b1[ch0 + ar + 8];
        int hr = ch0 + ar;
        #pragma unroll
        for(int ns=0; ns<4; ++ns){
            float acc[2][4] = {};
            #pragma unroll
            for(int ks=0;ks<8;++ks){
                uint32_t Bv[4];
                ldsmx4t(Bv, s2u(&Xs[(ks*16 + (lane&7) + ((lane>>3)&1)*8)*LDH2 + ns*16 + ((lane>>4)&1)*8]));
                mma_bf16(acc[0], Wf[ks], Bv);
                mma_bf16(acc[1], Wf[ks], Bv+2);
            }
            #pragma unroll
            for(int nh=0; nh<2; ++nh){
                int cc = ns*16 + nh*8 + ac;
                *(__nv_bfloat162*)&Hs[hr*LDH2 + cc] =
                    __floats2bfloat162_rn(gelu_f(acc[nh][0]+bb0), gelu_f(acc[nh][1]+bb0));
                *(__nv_bfloat162*)&Hs[(hr+8)*LDH2 + cc] =
                    __floats2bfloat162_rn(gelu_f(acc[nh][2]+bb1), gelu_f(acc[nh][3]+bb1));
            }
        }
    }
    __syncthreads();   // Hs ready for all warps
    // ---- GEMM2: z = W2 * hid; warps 8m x 2n; W2 fragments from gmem -------
    float zacc[2][2][4];
    #pragma unroll
    for(int a=0;a<2;++a)
        #pragma unroll
        for(int c=0;c<2;++c){ zacc[a][c][0]=0.f; zacc[a][c][1]=0.f;
                              zacc[a][c][2]=0.f; zacc[a][c][3]=0.f; }
    int m0b = (warp&7)*16, nb2 = (warp>>3)*32;
    const __nv_bfloat16* w2p = g_W2 + (size_t)m0b*MLP_;
    #pragma unroll 4
    for(int kc=0; kc<32; ++kc){
        int k0 = kc*16;
        uint32_t Af[4];
        const __nv_bfloat16* wp = w2p + k0;
        Af[0] = *(const uint32_t*)(wp + (size_t)(ar  )*MLP_ + ac);
        Af[1] = *(const uint32_t*)(wp + (size_t)(ar+8)*MLP_ + ac);
        Af[2] = *(const uint32_t*)(wp + (size_t)(ar  )*MLP_ + ac + 8);
        Af[3] = *(const uint32_t*)(wp + (size_t)(ar+8)*MLP_ + ac + 8);
        #pragma unroll
        for(int nt=0; nt<2; ++nt){
            uint32_t Bv[4];
            ldsmx4t(Bv, s2u(&Hs[(k0 + (lane&7) + ((lane>>3)&1)*8)*LDH2 + nb2 + nt*16 + ((lane>>4)&1)*8]));
            mma_bf16(zacc[nt][0], Af, Bv);
            mma_bf16(zacc[nt][1], Af, Bv+2);
        }
    }
    // ---- epilogue: z = x1 + zacc + b2 (fp32 stats, fp16 store) ----
    __half* zb = g_z + (size_t)b*NEL + n0;
    int rz = m0b + ar;
    float bz0 = b2[rz], bz1 = b2[rz+8];
    float ls = 0.f, lq = 0.f;
    #pragma unroll
    for(int nt=0; nt<2; ++nt){
        #pragma unroll
        for(int nh=0; nh<2; ++nh){
            int cc = nb2 + nt*16 + nh*8 + ac;
            float2 xa = __half22float2(*(const __half2*)&X1h[rz*LDXH + cc]);
            float2 xc = __half22float2(*(const __half2*)&X1h[(rz+8)*LDXH + cc]);
            float z00 = xa.x + zacc[nt][nh][0] + bz0;
            float z01 = xa.y + zacc[nt][nh][1] + bz0;
            float z10 = xc.x + zacc[nt][nh][2] + bz1;
            float z11 = xc.y + zacc[nt][nh][3] + bz1;
            *(__half2*)(zb + (size_t)rz*N_ + cc)     = __floats2half2_rn(z00, z01);
            *(__half2*)(zb + (size_t)(rz+8)*N_ + cc) = __floats2half2_rn(z10, z11);
            ls += z00+z01+z10+z11;
            lq += z00*z00 + z01*z01 + z10*z10 + z11*z11;
        }
    }
    #pragma unroll
    for(int o=16;o>0;o>>=1){ ls += __shfl_xor_sync(0xffffffffu, ls, o);
                             lq += __shfl_xor_sync(0xffffffffu, lq, o); }
    if(lane==0){ atomicAdd(&g_stats[2][b], ls); atomicAdd(&g_stats[3][b], lq); }
}

// ---------------- K8: out = LN2(z) (z fp16) --------------------------------
__global__ void __launch_bounds__(256) k_out(const float* __restrict__ w,
                                             const float* __restrict__ bb,
                                             float* __restrict__ out){
    size_t nv = (size_t)NEL/4;
    size_t st = (size_t)gridDim.x*blockDim.x;
    for(size_t v = (size_t)blockIdx.x*blockDim.x + threadIdx.x; v < nv; v += st){
        size_t t = v*4;
        float4 wv = *(const float4*)(w + t);
        float4 bv = *(const float4*)(bb + t);
        #pragma unroll
        for(int b=0;b<B_;++b){
            float mu = g_norm[2][b], rs = g_norm[3][b];
            const __half2* zp = (const __half2*)(g_z + (size_t)b*NEL + t);
            float2 zl = __half22float2(zp[0]);
            float2 zh = __half22float2(zp[1]);
            float4 o;
            o.x = (zl.x-mu)*rs*wv.x + bv.x;
            o.y = (zl.y-mu)*rs*wv.y + bv.y;
            o.z = (zh.x-mu)*rs*wv.z + bv.z;
            o.w = (zh.y-mu)*rs*wv.w + bv.w;
            *(float4*)(out + (size_t)b*NEL + t) = o;
        }
    }
}

// ---------------- launch ----------------------------------------------------
extern "C" void kernel_launch(void* const* d_in, const int* in_sizes, int n_in,
                              void* d_out, int out_size){
    const float* x      = (const float*)d_in[0];
    const float* qkv_w  = (const float*)d_in[1];
    const float* proj_w = (const float*)d_in[2];
    const float* proj_b = (const float*)d_in[3];
    const float* ln1w   = (const float*)d_in[4];
    const float* ln1b   = (const float*)d_in[5];
    const float* ln2w   = (const float*)d_in[6];
    const float* ln2b   = (const float*)d_in[7];
    const float* w1     = (const float*)d_in[8];
    const float* b1     = (const float*)d_in[9];
    const float* w2     = (const float*)d_in[10];
    const float* b2     = (const float*)d_in[11];
    float* out = (float*)d_out;

    const int SM_A  = (16384 + 4*16*LDS_ + 256)*4;            // 100608
    const int SM_B  = (2*16384 + 2*16*LDS_ + 128 + 64)*4;     // 148864
    const int SM_AM = 73728 + 17408 + 18432;                  // 109568
    cudaFuncSetAttribute(k_attA, cudaFuncAttributeMaxDynamicSharedMemorySize, SM_A);
    cudaFuncSetAttribute(k_attB, cudaFuncAttributeMaxDynamicSharedMemorySize, SM_B);
    cudaFuncSetAttribute(k_am,   cudaFuncAttributeMaxDynamicSharedMemorySize, SM_AM);

    k_init<<<256, 256>>>(w1, w2);
    k_gram<<<dim3(64, 8), 256>>>(x);
    k_attA<<<dim3(8, 8), 1024, SM_A>>>(qkv_w);
    k_attB<<<dim3(8, 8), 1024, SM_B>>>(proj_w, proj_b);
    k_norm<<<1, 32>>>(0);
    k_am<<<dim3(8, 512), 512, SM_AM>>>(x, proj_b, ln1w, ln1b, b1, b2);
    k_norm<<<1, 32>>>(1);
    k_out<<<4096, 256>>>(ln2w, ln2b, out);
}

// round 16
// speedup vs baseline: 1.2250x; 1.2250x over previous
#include <cuda_runtime.h>
#include <cuda_bf16.h>
#include <cuda_fp16.h>
#include <cstdint>
#include <math.h>

#define B_ 8
#define C_ 128
#define N_ 32768
#define NEL 4194304
#define MLP_ 512
#define EPS_ 1e-5f
#define SCALE_ 0.25f
#define LDE 136
#define LDH2 72
#define LDXH 68
#define GLD 72
#define LDS_ 133

// ---------------- scratch ----------------
__device__ float         g_G[B_][C_][C_];
__device__ float         g_M[B_][C_][C_];
__device__ float         g_s[B_][C_];
__device__ __nv_bfloat16 g_E[B_][C_][C_];
__device__ float         g_stats[4][B_];
__device__ float         g_norm[4][B_];
__device__ __nv_bfloat16 g_W1[MLP_*C_];
__device__ __nv_bfloat16 g_W2[C_*MLP_];
__device__ __half        g_z [(size_t)B_*NEL];

// ---------------- helpers ----------------
__device__ __forceinline__ uint32_t s2u(const void* p){
    return (uint32_t)__cvta_generic_to_shared(p);
}
__device__ __forceinline__ void ldsmx4(uint32_t* r, uint32_t a){
    asm volatile("ldmatrix.sync.aligned.m8n8.x4.shared.b16 {%0,%1,%2,%3},[%4];"
        : "=r"(r[0]),"=r"(r[1]),"=r"(r[2]),"=r"(r[3]) : "r"(a));
}
__device__ __forceinline__ void ldsmx4t(uint32_t* r, uint32_t a){
    asm volatile("ldmatrix.sync.aligned.m8n8.x4.trans.shared.b16 {%0,%1,%2,%3},[%4];"
        : "=r"(r[0]),"=r"(r[1]),"=r"(r[2]),"=r"(r[3]) : "r"(a));
}
__device__ __forceinline__ void mma_bf16(float* c, const uint32_t* a, const uint32_t* b){
    asm volatile("mma.sync.aligned.m16n8k16.row.col.f32.bf16.bf16.f32 "
        "{%0,%1,%2,%3},{%4,%5,%6,%7},{%8,%9},{%0,%1,%2,%3};"
        : "+f"(c[0]),"+f"(c[1]),"+f"(c[2]),"+f"(c[3])
        : "r"(a[0]),"r"(a[1]),"r"(a[2]),"r"(a[3]),"r"(b[0]),"r"(b[1]));
}
// fast GELU (tanh form): validated in R14, error contribution ~4e-5 rms.
__device__ __forceinline__ float gelu_f(float v){
    float u = 0.7978845608028654f*v*fmaf(0.044715f, v*v, 1.0f);
    return __fdividef(v, 1.0f + __expf(-2.0f*u));
}

// ---------------- K0 ----------------
__global__ void k_init(const float* __restrict__ w1, const float* __restrict__ w2){
    int i  = blockIdx.x*blockDim.x + threadIdx.x;
    int st = gridDim.x*blockDim.x;
    float* gg = &g_G[0][0][0];
    for(int t=i; t<B_*C_*C_; t+=st) gg[t] = 0.f;
    float* gsv = &g_s[0][0];
    for(int t=i; t<B_*C_; t+=st) gsv[t] = 0.f;
    float* gs = &g_stats[0][0];
    for(int t=i; t<4*B_; t+=st) gs[t] = 0.f;
    for(int t=i; t<MLP_*C_; t+=st) g_W1[t] = __float2bfloat16(w1[t]);
    for(int t=i; t<C_*MLP_; t+=st) g_W2[t] = __float2bfloat16(w2[t]);
}

// ---------------- K1: Gram G = X X^T (+ row sums); 64 splits ---------------
__global__ void __launch_bounds__(256) k_gram(const float* __restrict__ x){
    __shared__ __nv_bfloat16 Xs[C_][GLD];
    int b = blockIdx.y, split = blockIdx.x;
    const float* xb = x + (size_t)b*NEL + split*512;
    int tid = threadIdx.x, lane = tid&31, warp = tid>>5;
    float acc[16][4];
    #pragma unroll
    for(int i=0;i<16;++i){ acc[i][0]=acc[i][1]=acc[i][2]=acc[i][3]=0.f; }
    float racc[8] = {0.f,0.f,0.f,0.f,0.f,0.f,0.f,0.f};
    for(int kc=0; kc<8; ++kc){
        const float* src = xb + kc*64;
        #pragma unroll
        for(int m=0;m<8;++m){
            int idx = tid + m*256;
            int row = idx>>4, c4 = idx&15;
            float4 v = *(const float4*)(src + (size_t)row*N_ + c4*4);
            __nv_bfloat162* d = (__nv_bfloat162*)&Xs[row][c4*4];
            d[0] = __floats2bfloat162_rn(v.x, v.y);
            d[1] = __floats2bfloat162_rn(v.z, v.w);
            racc[m] += v.x+v.y+v.z+v.w;
        }
        __syncthreads();
        int m0 = warp*16;
        #pragma unroll
        for(int ks=0; ks<4; ++ks){
            int k = ks*16;
            uint32_t a[4];
            ldsmx4(a, s2u(&Xs[m0 + (lane&15)][k + ((lane>>4)&1)*8]));
            #pragma unroll
            for(int nt=0; nt<8; ++nt){
                uint32_t Bv[4];
                ldsmx4(Bv, s2u(&Xs[nt*16 + (lane&7) + ((lane>>4)&1)*8][k + ((lane>>3)&1)*8]));
                mma_bf16(acc[nt*2+0], a, Bv);
                mma_bf16(acc[nt*2+1], a, Bv+2);
            }
        }
        __syncthreads();
    }
    float* Gb = &g_G[b][0][0];
    int r0 = warp*16 + (lane>>2);
    #pragma unroll
    for(int nt=0; nt<16; ++nt){
        int c0 = nt*8 + (lane&3)*2;
        atomicAdd(&Gb[(size_t)r0*C_ + c0],       acc[nt][0]);
        atomicAdd(&Gb[(size_t)r0*C_ + c0+1],     acc[nt][1]);
        atomicAdd(&Gb[(size_t)(r0+8)*C_ + c0],   acc[nt][2]);
        atomicAdd(&Gb[(size_t)(r0+8)*C_ + c0+1], acc[nt][3]);
    }
    #pragma unroll
    for(int m=0;m<8;++m){
        #pragma unroll
        for(int o=8;o>0;o>>=1)
            racc[m] += __shfl_xor_sync(0xffffffffu, racc[m], o, 16);
    }
    if((tid&15)==0){
        int rb = tid>>4;
        #pragma unroll
        for(int m=0;m<8;++m)
            atomicAdd(&g_s[b][rb + 16*m], racc[m]);
    }
}

// ---------------- K2a ----------------
__global__ void __launch_bounds__(1024) k_attA(const float* __restrict__ qkv_w){
    extern __shared__ float sa[];
    float* Gs  = sa;
    float* Wq  = Gs + 16384;
    float* Wk  = Wq + 16*LDS_;
    float* Wv  = Wk + 16*LDS_;
    float* Ts  = Wv + 16*LDS_;
    float* As  = Ts + 16*LDS_;
    int h = blockIdx.x, b = blockIdx.y, tid = threadIdx.x;
    int r0 = h*16;
    const float* Gb = &g_G[b][0][0];
    for(int i=tid; i<4096; i+=1024)
        *(float4*)&Gs[i*4] = *(const float4*)&Gb[i*4];
    for(int i=tid; i<2048; i+=1024){
        int r = i>>7, c = i&127;
        Wq[r*LDS_+c] = qkv_w[(size_t)(r0+r)*C_ + c];
        Wk[r*LDS_+c] = qkv_w[(size_t)(C_+r0+r)*C_ + c];
        Wv[r*LDS_+c] = qkv_w[(size_t)(2*C_+r0+r)*C_ + c];
    }
    __syncthreads();
    int il = tid>>6, tg = tid&63;
    {
        float a0 = 0.f, a1 = 0.f;
        #pragma unroll 4
        for(int k=0;k<C_;++k){
            float w = Wq[il*LDS_+k];
            a0 += w*Gs[k*128 + tg];
            a1 += w*Gs[k*128 + tg + 64];
        }
        Ts[il*LDS_ + tg]      = a0;
        Ts[il*LDS_ + tg + 64] = a1;
    }
    __syncthreads();
    if(tid < 256){
        int ir = tid>>4, jg = tid&15;
        float l = 0.f;
        #pragma unroll 4
        for(int t=0;t<C_;++t) l += Ts[ir*LDS_+t]*Wk[jg*LDS_+t];
        l *= SCALE_;
        float mx = l;
        #pragma unroll
        for(int o=8;o>0;o>>=1) mx = fmaxf(mx, __shfl_xor_sync(0xffffffffu, mx, o, 16));
        float e = expf(l-mx), s = e;
        #pragma unroll
        for(int o=8;o>0;o>>=1) s += __shfl_xor_sync(0xffffffffu, s, o, 16);
        As[ir*16+jg] = e/s;
    }
    __syncthreads();
    {
        float a0 = 0.f, a1 = 0.f;
        #pragma unroll
        for(int j=0;j<16;++j){
            float a = As[il*16+j];
            a0 += a*Wv[j*LDS_ + tg];
            a1 += a*Wv[j*LDS_ + tg + 64];
        }
        g_M[b][r0+il][tg]      = a0;
        g_M[b][r0+il][tg + 64] = a1;
    }
}

// ---------------- K2b ----------------
__global__ void __launch_bounds__(1024) k_attB(const float* __restrict__ proj_w,
                                               const float* __restrict__ proj_b){
    extern __shared__ float sb[];
    float* Gs  = sb;
    float* MS  = Gs + 16384;
    float* Wp  = MS + 16384;
    float* Es  = Wp + 16*LDS_;
    float* sv  = Es + 16*LDS_;
    float* red = sv + 128;
    int rg = blockIdx.x, b = blockIdx.y, tid = threadIdx.x;
    int r0 = rg*16;
    const float* Gb = &g_G[b][0][0];
    const float* Mb = &g_M[b][0][0];
    for(int i=tid; i<4096; i+=1024){
        *(float4*)&Gs[i*4] = *(const float4*)&Gb[i*4];
        *(float4*)&MS[i*4] = *(const float4*)&Mb[i*4];
    }
    for(int i=tid; i<2048; i+=1024){
        int r = i>>7, c = i&127;
        Wp[r*LDS_+c] = proj_w[(size_t)(r0+r)*C_ + c];
    }
    if(tid<128) sv[tid] = g_s[b][tid];
    __syncthreads();
    int ol = tid>>6, tg = tid&63;
    {
        float a0 = 0.f, a1 = 0.f;
        #pragma unroll 4
        for(int r=0;r<C_;++r){
            float w = Wp[ol*LDS_+r];
            a0 += w*MS[r*128 + tg];
            a1 += w*MS[r*128 + tg + 64];
        }
        int og = r0 + ol;
        g_E[b][og][tg]      = __float2bfloat16(a0);
        g_E[b][og][tg + 64] = __float2bfloat16(a1);
        Es[ol*LDS_ + tg]      = a0 + ((og==tg)      ? 1.f : 0.f);
        Es[ol*LDS_ + tg + 64] = a1 + ((og==tg+64)   ? 1.f : 0.f);
    }
    __syncthreads();
    {
        float q = 0.f, ms = 0.f;
        #pragma unroll
        for(int tt=0;tt<2;++tt){
            int j = tg + tt*64;
            float p = 0.f;
            #pragma unroll 4
            for(int i=0;i<C_;++i) p += Es[ol*LDS_+i]*Gs[i*128 + j];
            float rj = Es[ol*LDS_+j];
            q  += p*rj;
            ms += rj*sv[j];
        }
        #pragma unroll
        for(int o=16;o>0;o>>=1){
            q  += __shfl_xor_sync(0xffffffffu, q,  o);
            ms += __shfl_xor_sync(0xffffffffu, ms, o);
        }
        int wh = (tid>>5)&1;
        if((tid&31)==0){
            red[ol*2 + wh]      = q;
            red[32 + ol*2 + wh] = ms;
        }
    }
    __syncthreads();
    if(tid < 16){
        float q  = red[tid*2] + red[tid*2+1];
        float ms = red[32+tid*2] + red[32+tid*2+1];
        float pb = proj_b[r0+tid];
        float qf = q + 2.f*pb*ms + (float)N_*pb*pb;
        float sf = ms + (float)N_*pb;
        #pragma unroll
        for(int o=8;o>0;o>>=1){
            qf += __shfl_xor_sync(0xffffu, qf, o, 16);
            sf += __shfl_xor_sync(0xffffu, sf, o, 16);
        }
        if(tid==0){
            atomicAdd(&g_stats[1][b], qf);
            atomicAdd(&g_stats[0][b], sf);
        }
    }
}

// ---------------- K5/K7 ----------------
__global__ void k_norm(int stage){
    int b = threadIdx.x;
    if(b < B_){
        float s = g_stats[stage*2][b], q = g_stats[stage*2+1][b];
        float mu = s / (float)NEL;
        float var = q / (float)NEL - mu*mu;
        g_norm[stage*2][b]   = mu;
        g_norm[stage*2+1][b] = rsqrtf(var + EPS_);
    }
}

// ---------------- K6: fused apply + LN1 + MLP (exact R13 structure) --------
// 64-wide tile, 512 thr, 107KB smem -> 2 CTAs/SM; x1 residual fp16;
// GEMM2 staged W2 through smem (64-k chunks).
__global__ void __launch_bounds__(512,2) k_am(const float* __restrict__ x,
                                              const float* __restrict__ proj_b,
                                              const float* __restrict__ ln1w,
                                              const float* __restrict__ ln1b,
                                              const float* __restrict__ b1,
                                              const float* __restrict__ b2){
    extern __shared__ char smraw[];
    __nv_bfloat16* Hs  = (__nv_bfloat16*)smraw;                    // 512*72*2 = 73728 (Es first)
    __half*        X1h = (__half*)(smraw + 73728);                 // 128*68*2 = 17408
    __nv_bfloat16* Xs  = (__nv_bfloat16*)(smraw + 73728 + 17408);  // 128*72*2 = 18432 (W2s later)
    __nv_bfloat16* Es  = Hs;
    __nv_bfloat16* W2s = Xs;
    int b = blockIdx.x, n0 = blockIdx.y*64;
    int tid = threadIdx.x, lane = tid&31, warp = tid>>5;   // 16 warps
    const float* xb = x + (size_t)b*NEL + n0;
    // stage E (128x128 bf16) and x tile (128x64 bf16)
    #pragma unroll
    for(int m=0;m<4;++m){
        int idx = tid + m*512;
        int r = idx>>4, c8 = (idx&15)*8;
        *(uint4*)&Es[r*LDE + c8] = *(const uint4*)&g_E[b][r][c8];
    }
    #pragma unroll
    for(int m=0;m<4;++m){
        int idx = tid + m*512;
        int r = idx>>4, c4 = (idx&15)*4;
        float4 v = *(const float4*)(xb + (size_t)r*N_ + c4);
        __nv_bfloat162* d = (__nv_bfloat162*)&Xs[r*LDH2 + c4];
        d[0] = __floats2bfloat162_rn(v.x, v.y);
        d[1] = __floats2bfloat162_rn(v.z, v.w);
    }
    __syncthreads();
    int ar = lane>>2, ac = (lane&3)*2;
    float mu1 = g_norm[0][b], rs1 = g_norm[1][b];
    // ---- phase A: two 16x16 tiles per warp
    float xv[2][2][4];
    #pragma unroll
    for(int t=0;t<2;++t){
        int w2 = warp + t*16;
        int m0 = (w2&7)*16, n = (w2>>3)*16;
        int r0 = m0 + ar;
        uint32_t A8[8][4];
        #pragma unroll
        for(int ks=0; ks<8; ++ks)
            ldsmx4(A8[ks], s2u(&Es[(m0 + (lane&15))*LDE + ks*16 + ((lane>>4)&1)*8]));
        float acc[2][4] = {};
        #pragma unroll
        for(int ks=0; ks<8; ++ks){
            uint32_t Bv[4];
            ldsmx4t(Bv, s2u(&Xs[(ks*16 + (lane&7) + ((lane>>3)&1)*8)*LDH2 + n + ((lane>>4)&1)*8]));
            mma_bf16(acc[0], A8[ks], Bv);
            mma_bf16(acc[1], A8[ks], Bv+2);
        }
        float pb0 = proj_b[r0], pb1 = proj_b[r0+8];
        #pragma unroll
        for(int nh=0; nh<2; ++nh){
            int cc = n + nh*8 + ac;
            float2 x0  = *(const float2*)(xb + (size_t)r0*N_ + cc);
            float2 x1v = *(const float2*)(xb + (size_t)(r0+8)*N_ + cc);
            float y00 = x0.x  + acc[nh][0] + pb0;
            float y01 = x0.y  + acc[nh][1] + pb0;
            float y10 = x1v.x + acc[nh][2] + pb1;
            float y11 = x1v.y + acc[nh][3] + pb1;
            float2 w0 = *(const float2*)(ln1w + (size_t)r0*N_ + n0 + cc);
            float2 w1 = *(const float2*)(ln1w + (size_t)(r0+8)*N_ + n0 + cc);
            float2 g0 = *(const float2*)(ln1b + (size_t)r0*N_ + n0 + cc);
            float2 g1 = *(const float2*)(ln1b + (size_t)(r0+8)*N_ + n0 + cc);
            xv[t][nh][0] = (y00-mu1)*rs1*w0.x + g0.x;
            xv[t][nh][1] = (y01-mu1)*rs1*w0.y + g0.y;
            xv[t][nh][2] = (y10-mu1)*rs1*w1.x + g1.x;
            xv[t][nh][3] = (y11-mu1)*rs1*w1.y + g1.y;
        }
    }
    __syncthreads();
    // ---- phase B: store x1 (fp16 residual + bf16 mma input)
    #pragma unroll
    for(int t=0;t<2;++t){
        int w2 = warp + t*16;
        int m0 = (w2&7)*16, n = (w2>>3)*16;
        int r0 = m0 + ar;
        #pragma unroll
        for(int nh=0; nh<2; ++nh){
            int cc = n + nh*8 + ac;
            *(__half2*)&X1h[r0*LDXH + cc]     = __floats2half2_rn(xv[t][nh][0], xv[t][nh][1]);
            *(__half2*)&X1h[(r0+8)*LDXH + cc] = __floats2half2_rn(xv[t][nh][2], xv[t][nh][3]);
            *(__nv_bfloat162*)&Xs[r0*LDH2 + cc]     = __floats2bfloat162_rn(xv[t][nh][0], xv[t][nh][1]);
            *(__nv_bfloat162*)&Xs[(r0+8)*LDH2 + cc] = __floats2bfloat162_rn(xv[t][nh][2], xv[t][nh][3]);
        }
    }
    __syncthreads();
    // ---- GEMM1: hid = gelu(W1 x1 + b1): 16 warps x 2 groups of 16 rows
    #pragma unroll
    for(int g=0; g<2; ++g){
        int ch0 = warp*16 + g*256;
        uint32_t Wf[8][4];
        const __nv_bfloat16* w1p = g_W1 + (size_t)ch0*C_;
        #pragma unroll
        for(int ks=0;ks<8;++ks){
            const __nv_bfloat16* wp = w1p + ks*16;
            Wf[ks][0] = *(const uint32_t*)(wp + (size_t)(ar  )*C_ + ac);
            Wf[ks][1] = *(const uint32_t*)(wp + (size_t)(ar+8)*C_ + ac);
            Wf[ks][2] = *(const uint32_t*)(wp + (size_t)(ar  )*C_ + ac + 8);
            Wf[ks][3] = *(const uint32_t*)(wp + (size_t)(ar+8)*C_ + ac + 8);
        }
        float bb0 = b1[ch0 + ar], bb1 = b1[ch0 + ar + 8];
        int hr = ch0 + ar;
        #pragma unroll
        for(int ns=0; ns<4; ++ns){
            float acc[2][4] = {};
            #pragma unroll
            for(int ks=0;ks<8;++ks){
                uint32_t Bv[4];
                ldsmx4t(Bv, s2u(&Xs[(ks*16 + (lane&7) + ((lane>>3)&1)*8)*LDH2 + ns*16 + ((lane>>4)&1)*8]));
                mma_bf16(acc[0], Wf[ks], Bv);
                mma_bf16(acc[1], Wf[ks], Bv+2);
            }
            #pragma unroll
            for(int nh=0; nh<2; ++nh){
                int cc = ns*16 + nh*8 + ac;
                *(__nv_bfloat162*)&Hs[hr*LDH2 + cc] =
                    __floats2bfloat162_rn(gelu_f(acc[nh][0]+bb0), gelu_f(acc[nh][1]+bb0));
                *(__nv_bfloat162*)&Hs[(hr+8)*LDH2 + cc] =
                    __floats2bfloat162_rn(gelu_f(acc[nh][2]+bb1), gelu_f(acc[nh][3]+bb1));
            }
        }
    }
    // ---- GEMM2: z = W2 * hid; warps 8m x 2n (16m x 32n tiles), 64-k chunks
    float zacc[2][2][4];
    #pragma unroll
    for(int a=0;a<2;++a)
        #pragma unroll
        for(int c=0;c<2;++c){ zacc[a][c][0]=0.f; zacc[a][c][1]=0.f;
                              zacc[a][c][2]=0.f; zacc[a][c][3]=0.f; }
    int m0b = (warp&7)*16, nb2 = (warp>>3)*32;
    for(int c0=0; c0<MLP_; c0+=64){
        __syncthreads();
        #pragma unroll
        for(int m=0;m<2;++m){
            int idx = tid + m*512;
            int r = idx>>3, u = idx&7;
            *(uint4*)&W2s[r*LDH2 + u*8] = *(const uint4*)&g_W2[(size_t)r*MLP_ + c0 + u*8];
        }
        __syncthreads();
        #pragma unroll
        for(int ks2=0; ks2<4; ++ks2){
            uint32_t Af[4];
            ldsmx4(Af, s2u(&W2s[(m0b + (lane&15))*LDH2 + ks2*16 + ((lane>>4)&1)*8]));
            #pragma unroll
            for(int nt=0; nt<2; ++nt){
                uint32_t Bv[4];
                ldsmx4t(Bv, s2u(&Hs[(c0 + ks2*16 + (lane&7) + ((lane>>3)&1)*8)*LDH2 + nb2 + nt*16 + ((lane>>4)&1)*8]));
                mma_bf16(zacc[nt][0], Af, Bv);
                mma_bf16(zacc[nt][1], Af, Bv+2);
            }
        }
    }
    // ---- epilogue: z = x1 + zacc + b2 (fp32 stats, fp16 store) ----
    __half* zb = g_z + (size_t)b*NEL + n0;
    int rz = m0b + ar;
    float bz0 = b2[rz], bz1 = b2[rz+8];
    float ls = 0.f, lq = 0.f;
    #pragma unroll
    for(int nt=0; nt<2; ++nt){
        #pragma unroll
        for(int nh=0; nh<2; ++nh){
            int cc = nb2 + nt*16 + nh*8 + ac;
            float2 xa = __half22float2(*(const __half2*)&X1h[rz*LDXH + cc]);
            float2 xc = __half22float2(*(const __half2*)&X1h[(rz+8)*LDXH + cc]);
            float z00 = xa.x + zacc[nt][nh][0] + bz0;
            float z01 = xa.y + zacc[nt][nh][1] + bz0;
            float z10 = xc.x + zacc[nt][nh][2] + bz1;
            float z11 = xc.y + zacc[nt][nh][3] + bz1;
            *(__half2*)(zb + (size_t)rz*N_ + cc)     = __floats2half2_rn(z00, z01);
            *(__half2*)(zb + (size_t)(rz+8)*N_ + cc) = __floats2half2_rn(z10, z11);
            ls += z00+z01+z10+z11;
            lq += z00*z00 + z01*z01 + z10*z10 + z11*z11;
        }
    }
    #pragma unroll
    for(int o=16;o>0;o>>=1){ ls += __shfl_xor_sync(0xffffffffu, ls, o);
                             lq += __shfl_xor_sync(0xffffffffu, lq, o); }
    if(lane==0){ atomicAdd(&g_stats[2][b], ls); atomicAdd(&g_stats[3][b], lq); }
}

// ---------------- K8: out = LN2(z) (z fp16) --------------------------------
__global__ void __launch_bounds__(256) k_out(const float* __restrict__ w,
                                             const float* __restrict__ bb,
                                             float* __restrict__ out){
    size_t nv = (size_t)NEL/4;
    size_t st = (size_t)gridDim.x*blockDim.x;
    for(size_t v = (size_t)blockIdx.x*blockDim.x + threadIdx.x; v < nv; v += st){
        size_t t = v*4;
        float4 wv = *(const float4*)(w + t);
        float4 bv = *(const float4*)(bb + t);
        #pragma unroll
        for(int b=0;b<B_;++b){
            float mu = g_norm[2][b], rs = g_norm[3][b];
            const __half2* zp = (const __half2*)(g_z + (size_t)b*NEL + t);
            float2 zl = __half22float2(zp[0]);
            float2 zh = __half22float2(zp[1]);
            float4 o;
            o.x = (zl.x-mu)*rs*wv.x + bv.x;
            o.y = (zl.y-mu)*rs*wv.y + bv.y;
            o.z = (zh.x-mu)*rs*wv.z + bv.z;
            o.w = (zh.y-mu)*rs*wv.w + bv.w;
            *(float4*)(out + (size_t)b*NEL + t) = o;
        }
    }
}

// ---------------- launch ----------------------------------------------------
extern "C" void kernel_launch(void* const* d_in, const int* in_sizes, int n_in,
                              void* d_out, int out_size){
    const float* x      = (const float*)d_in[0];
    const float* qkv_w  = (const float*)d_in[1];
    const float* proj_w = (const float*)d_in[2];
    const float* proj_b = (const float*)d_in[3];
    const float* ln1w   = (const float*)d_in[4];
    const float* ln1b   = (const float*)d_in[5];
    const float* ln2w   = (const float*)d_in[6];
    const float* ln2b   = (const float*)d_in[7];
    const float* w1     = (const float*)d_in[8];
    const float* b1     = (const float*)d_in[9];
    const float* w2     = (const float*)d_in[10];
    const float* b2     = (const float*)d_in[11];
    float* out = (float*)d_out;

    const int SM_A  = (16384 + 4*16*LDS_ + 256)*4;            // 100608
    const int SM_B  = (2*16384 + 2*16*LDS_ + 128 + 64)*4;     // 148864
    const int SM_AM = 73728 + 17408 + 18432;                  // 109568
    cudaFuncSetAttribute(k_attA, cudaFuncAttributeMaxDynamicSharedMemorySize, SM_A);
    cudaFuncSetAttribute(k_attB, cudaFuncAttributeMaxDynamicSharedMemorySize, SM_B);
    cudaFuncSetAttribute(k_am,   cudaFuncAttributeMaxDynamicSharedMemorySize, SM_AM);

    k_init<<<256, 256>>>(w1, w2);
    k_gram<<<dim3(64, 8), 256>>>(x);
    k_attA<<<dim3(8, 8), 1024, SM_A>>>(qkv_w);
    k_attB<<<dim3(8, 8), 1024, SM_B>>>(proj_w, proj_b);
    k_norm<<<1, 32>>>(0);
    k_am<<<dim3(8, 512), 512, SM_AM>>>(x, proj_b, ln1w, ln1b, b1, b2);
    k_norm<<<1, 32>>>(1);
    k_out<<<4096, 256>>>(ln2w, ln2b, out);
}

// round 17
// speedup vs baseline: 1.2495x; 1.0200x over previous
#include <cuda_runtime.h>
#include <cuda_bf16.h>
#include <cuda_fp16.h>
#include <cstdint>
#include <math.h>

#define B_ 8
#define C_ 128
#define N_ 32768
#define NEL 4194304
#define MLP_ 512
#define EPS_ 1e-5f
#define SCALE_ 0.25f
#define LDE 136
#define LDH2 72
#define LDXH 68
#define GLD 72
#define LDS_ 133

// ---------------- scratch ----------------
__device__ float         g_G[B_][C_][C_];
__device__ float         g_M[B_][C_][C_];
__device__ float         g_s[B_][C_];
__device__ __nv_bfloat16 g_E[B_][C_][C_];
__device__ float         g_stats[4][B_];
__device__ __nv_bfloat16 g_W1[MLP_*C_];
__device__ __nv_bfloat16 g_W2[C_*MLP_];
__device__ __half        g_z [(size_t)B_*NEL];

// ---------------- helpers ----------------
__device__ __forceinline__ uint32_t s2u(const void* p){
    return (uint32_t)__cvta_generic_to_shared(p);
}
__device__ __forceinline__ void ldsmx4(uint32_t* r, uint32_t a){
    asm volatile("ldmatrix.sync.aligned.m8n8.x4.shared.b16 {%0,%1,%2,%3},[%4];"
        : "=r"(r[0]),"=r"(r[1]),"=r"(r[2]),"=r"(r[3]) : "r"(a));
}
__device__ __forceinline__ void ldsmx4t(uint32_t* r, uint32_t a){
    asm volatile("ldmatrix.sync.aligned.m8n8.x4.trans.shared.b16 {%0,%1,%2,%3},[%4];"
        : "=r"(r[0]),"=r"(r[1]),"=r"(r[2]),"=r"(r[3]) : "r"(a));
}
__device__ __forceinline__ void mma_bf16(float* c, const uint32_t* a, const uint32_t* b){
    asm volatile("mma.sync.aligned.m16n8k16.row.col.f32.bf16.bf16.f32 "
        "{%0,%1,%2,%3},{%4,%5,%6,%7},{%8,%9},{%0,%1,%2,%3};"
        : "+f"(c[0]),"+f"(c[1]),"+f"(c[2]),"+f"(c[3])
        : "r"(a[0]),"r"(a[1]),"r"(a[2]),"r"(a[3]),"r"(b[0]),"r"(b[1]));
}
// fast GELU (tanh form): error contribution ~4e-5 rms (validated R14/R15).
__device__ __forceinline__ float gelu_f(float v){
    float u = 0.7978845608028654f*v*fmaf(0.044715f, v*v, 1.0f);
    return __fdividef(v, 1.0f + __expf(-2.0f*u));
}

// ---------------- K0 ----------------
__global__ void k_init(const float* __restrict__ w1, const float* __restrict__ w2){
    int i  = blockIdx.x*blockDim.x + threadIdx.x;
    int st = gridDim.x*blockDim.x;
    float* gg = &g_G[0][0][0];
    for(int t=i; t<B_*C_*C_; t+=st) gg[t] = 0.f;
    float* gsv = &g_s[0][0];
    for(int t=i; t<B_*C_; t+=st) gsv[t] = 0.f;
    float* gs = &g_stats[0][0];
    for(int t=i; t<4*B_; t+=st) gs[t] = 0.f;
    for(int t=i; t<MLP_*C_; t+=st) g_W1[t] = __float2bfloat16(w1[t]);
    for(int t=i; t<C_*MLP_; t+=st) g_W2[t] = __float2bfloat16(w2[t]);
}

// ---------------- K1: Gram G = X X^T (+ row sums); 64 splits ---------------
__global__ void __launch_bounds__(256) k_gram(const float* __restrict__ x){
    __shared__ __nv_bfloat16 Xs[C_][GLD];
    int b = blockIdx.y, split = blockIdx.x;
    const float* xb = x + (size_t)b*NEL + split*512;
    int tid = threadIdx.x, lane = tid&31, warp = tid>>5;
    float acc[16][4];
    #pragma unroll
    for(int i=0;i<16;++i){ acc[i][0]=acc[i][1]=acc[i][2]=acc[i][3]=0.f; }
    float racc[8] = {0.f,0.f,0.f,0.f,0.f,0.f,0.f,0.f};
    for(int kc=0; kc<8; ++kc){
        const float* src = xb + kc*64;
        #pragma unroll
        for(int m=0;m<8;++m){
            int idx = tid + m*256;
            int row = idx>>4, c4 = idx&15;
            float4 v = *(const float4*)(src + (size_t)row*N_ + c4*4);
            __nv_bfloat162* d = (__nv_bfloat162*)&Xs[row][c4*4];
            d[0] = __floats2bfloat162_rn(v.x, v.y);
            d[1] = __floats2bfloat162_rn(v.z, v.w);
            racc[m] += v.x+v.y+v.z+v.w;
        }
        __syncthreads();
        int m0 = warp*16;
        #pragma unroll
        for(int ks=0; ks<4; ++ks){
            int k = ks*16;
            uint32_t a[4];
            ldsmx4(a, s2u(&Xs[m0 + (lane&15)][k + ((lane>>4)&1)*8]));
            #pragma unroll
            for(int nt=0; nt<8; ++nt){
                uint32_t Bv[4];
                ldsmx4(Bv, s2u(&Xs[nt*16 + (lane&7) + ((lane>>4)&1)*8][k + ((lane>>3)&1)*8]));
                mma_bf16(acc[nt*2+0], a, Bv);
                mma_bf16(acc[nt*2+1], a, Bv+2);
            }
        }
        __syncthreads();
    }
    float* Gb = &g_G[b][0][0];
    int r0 = warp*16 + (lane>>2);
    #pragma unroll
    for(int nt=0; nt<16; ++nt){
        int c0 = nt*8 + (lane&3)*2;
        atomicAdd(&Gb[(size_t)r0*C_ + c0],       acc[nt][0]);
        atomicAdd(&Gb[(size_t)r0*C_ + c0+1],     acc[nt][1]);
        atomicAdd(&Gb[(size_t)(r0+8)*C_ + c0],   acc[nt][2]);
        atomicAdd(&Gb[(size_t)(r0+8)*C_ + c0+1], acc[nt][3]);
    }
    #pragma unroll
    for(int m=0;m<8;++m){
        #pragma unroll
        for(int o=8;o>0;o>>=1)
            racc[m] += __shfl_xor_sync(0xffffffffu, racc[m], o, 16);
    }
    if((tid&15)==0){
        int rb = tid>>4;
        #pragma unroll
        for(int m=0;m<8;++m)
            atomicAdd(&g_s[b][rb + 16*m], racc[m]);
    }
}

// ---------------- K2a ----------------
__global__ void __launch_bounds__(1024) k_attA(const float* __restrict__ qkv_w){
    extern __shared__ float sa[];
    float* Gs  = sa;
    float* Wq  = Gs + 16384;
    float* Wk  = Wq + 16*LDS_;
    float* Wv  = Wk + 16*LDS_;
    float* Ts  = Wv + 16*LDS_;
    float* As  = Ts + 16*LDS_;
    int h = blockIdx.x, b = blockIdx.y, tid = threadIdx.x;
    int r0 = h*16;
    const float* Gb = &g_G[b][0][0];
    for(int i=tid; i<4096; i+=1024)
        *(float4*)&Gs[i*4] = *(const float4*)&Gb[i*4];
    for(int i=tid; i<2048; i+=1024){
        int r = i>>7, c = i&127;
        Wq[r*LDS_+c] = qkv_w[(size_t)(r0+r)*C_ + c];
        Wk[r*LDS_+c] = qkv_w[(size_t)(C_+r0+r)*C_ + c];
        Wv[r*LDS_+c] = qkv_w[(size_t)(2*C_+r0+r)*C_ + c];
    }
    __syncthreads();
    int il = tid>>6, tg = tid&63;
    {
        float a0 = 0.f, a1 = 0.f;
        #pragma unroll 4
        for(int k=0;k<C_;++k){
            float w = Wq[il*LDS_+k];
            a0 += w*Gs[k*128 + tg];
            a1 += w*Gs[k*128 + tg + 64];
        }
        Ts[il*LDS_ + tg]      = a0;
        Ts[il*LDS_ + tg + 64] = a1;
    }
    __syncthreads();
    if(tid < 256){
        int ir = tid>>4, jg = tid&15;
        float l = 0.f;
        #pragma unroll 4
        for(int t=0;t<C_;++t) l += Ts[ir*LDS_+t]*Wk[jg*LDS_+t];
        l *= SCALE_;
        float mx = l;
        #pragma unroll
        for(int o=8;o>0;o>>=1) mx = fmaxf(mx, __shfl_xor_sync(0xffffffffu, mx, o, 16));
        float e = expf(l-mx), s = e;
        #pragma unroll
        for(int o=8;o>0;o>>=1) s += __shfl_xor_sync(0xffffffffu, s, o, 16);
        As[ir*16+jg] = e/s;
    }
    __syncthreads();
    {
        float a0 = 0.f, a1 = 0.f;
        #pragma unroll
        for(int j=0;j<16;++j){
            float a = As[il*16+j];
            a0 += a*Wv[j*LDS_ + tg];
            a1 += a*Wv[j*LDS_ + tg + 64];
        }
        g_M[b][r0+il][tg]      = a0;
        g_M[b][r0+il][tg + 64] = a1;
    }
}

// ---------------- K2b ----------------
__global__ void __launch_bounds__(1024) k_attB(const float* __restrict__ proj_w,
                                               const float* __restrict__ proj_b){
    extern __shared__ float sb[];
    float* Gs  = sb;
    float* MS  = Gs + 16384;
    float* Wp  = MS + 16384;
    float* Es  = Wp + 16*LDS_;
    float* sv  = Es + 16*LDS_;
    float* red = sv + 128;
    int rg = blockIdx.x, b = blockIdx.y, tid = threadIdx.x;
    int r0 = rg*16;
    const float* Gb = &g_G[b][0][0];
    const float* Mb = &g_M[b][0][0];
    for(int i=tid; i<4096; i+=1024){
        *(float4*)&Gs[i*4] = *(const float4*)&Gb[i*4];
        *(float4*)&MS[i*4] = *(const float4*)&Mb[i*4];
    }
    for(int i=tid; i<2048; i+=1024){
        int r = i>>7, c = i&127;
        Wp[r*LDS_+c] = proj_w[(size_t)(r0+r)*C_ + c];
    }
    if(tid<128) sv[tid] = g_s[b][tid];
    __syncthreads();
    int ol = tid>>6, tg = tid&63;
    {
        float a0 = 0.f, a1 = 0.f;
        #pragma unroll 4
        for(int r=0;r<C_;++r){
            float w = Wp[ol*LDS_+r];
            a0 += w*MS[r*128 + tg];
            a1 += w*MS[r*128 + tg + 64];
        }
        int og = r0 + ol;
        g_E[b][og][tg]      = __float2bfloat16(a0);
        g_E[b][og][tg + 64] = __float2bfloat16(a1);
        Es[ol*LDS_ + tg]      = a0 + ((og==tg)      ? 1.f : 0.f);
        Es[ol*LDS_ + tg + 64] = a1 + ((og==tg+64)   ? 1.f : 0.f);
    }
    __syncthreads();
    {
        float q = 0.f, ms = 0.f;
        #pragma unroll
        for(int tt=0;tt<2;++tt){
            int j = tg + tt*64;
            float p = 0.f;
            #pragma unroll 4
            for(int i=0;i<C_;++i) p += Es[ol*LDS_+i]*Gs[i*128 + j];
            float rj = Es[ol*LDS_+j];
            q  += p*rj;
            ms += rj*sv[j];
        }
        #pragma unroll
        for(int o=16;o>0;o>>=1){
            q  += __shfl_xor_sync(0xffffffffu, q,  o);
            ms += __shfl_xor_sync(0xffffffffu, ms, o);
        }
        int wh = (tid>>5)&1;
        if((tid&31)==0){
            red[ol*2 + wh]      = q;
            red[32 + ol*2 + wh] = ms;
        }
    }
    __syncthreads();
    if(tid < 16){
        float q  = red[tid*2] + red[tid*2+1];
        float ms = red[32+tid*2] + red[32+tid*2+1];
        float pb = proj_b[r0+tid];
        float qf = q + 2.f*pb*ms + (float)N_*pb*pb;
        float sf = ms + (float)N_*pb;
        #pragma unroll
        for(int o=8;o>0;o>>=1){
            qf += __shfl_xor_sync(0xffffu, qf, o, 16);
            sf += __shfl_xor_sync(0xffffu, sf, o, 16);
        }
        if(tid==0){
            atomicAdd(&g_stats[1][b], qf);
            atomicAdd(&g_stats[0][b], sf);
        }
    }
}

// ---------------- K6: fused apply + LN1 + MLP ------------------------------
// LN1 stats finalized inline from g_stats (k_norm launch removed).
__global__ void __launch_bounds__(512,2) k_am(const float* __restrict__ x,
                                              const float* __restrict__ proj_b,
                                              const float* __restrict__ ln1w,
                                              const float* __restrict__ ln1b,
                                              const float* __restrict__ b1,
                                              const float* __restrict__ b2){
    extern __shared__ char smraw[];
    __nv_bfloat16* Hs  = (__nv_bfloat16*)smraw;                    // 73728 (Es first)
    __half*        X1h = (__half*)(smraw + 73728);                 // 17408
    __nv_bfloat16* Xs  = (__nv_bfloat16*)(smraw + 73728 + 17408);  // 18432 (W2s later)
    __nv_bfloat16* Es  = Hs;
    __nv_bfloat16* W2s = Xs;
    int b = blockIdx.x, n0 = blockIdx.y*64;
    int tid = threadIdx.x, lane = tid&31, warp = tid>>5;   // 16 warps
    const float* xb = x + (size_t)b*NEL + n0;
    // stage E (128x128 bf16) and x tile (128x64 bf16)
    #pragma unroll
    for(int m=0;m<4;++m){
        int idx = tid + m*512;
        int r = idx>>4, c8 = (idx&15)*8;
        *(uint4*)&Es[r*LDE + c8] = *(const uint4*)&g_E[b][r][c8];
    }
    #pragma unroll
    for(int m=0;m<4;++m){
        int idx = tid + m*512;
        int r = idx>>4, c4 = (idx&15)*4;
        float4 v = *(const float4*)(xb + (size_t)r*N_ + c4);
        __nv_bfloat162* d = (__nv_bfloat162*)&Xs[r*LDH2 + c4];
        d[0] = __floats2bfloat162_rn(v.x, v.y);
        d[1] = __floats2bfloat162_rn(v.z, v.w);
    }
    __syncthreads();
    int ar = lane>>2, ac = (lane&3)*2;
    // inline LN1 finalize
    float mu1, rs1;
    {
        float s = g_stats[0][b], q = g_stats[1][b];
        mu1 = s / (float)NEL;
        rs1 = rsqrtf(q / (float)NEL - mu1*mu1 + EPS_);
    }
    // ---- phase A: two 16x16 tiles per warp; SAME m-row-set both tiles ----
    int m0 = (warp&7)*16;
    int nA = (warp>>3)*16;          // tile 0: n = nA, tile 1: n = nA + 32
    int r0 = m0 + ar;
    float xv[2][2][4];
    {
        uint32_t A8[8][4];
        #pragma unroll
        for(int ks=0; ks<8; ++ks)
            ldsmx4(A8[ks], s2u(&Es[(m0 + (lane&15))*LDE + ks*16 + ((lane>>4)&1)*8]));
        float pb0 = proj_b[r0], pb1 = proj_b[r0+8];
        #pragma unroll
        for(int t=0;t<2;++t){
            int n = nA + t*32;
            float acc[2][4] = {};
            #pragma unroll
            for(int ks=0; ks<8; ++ks){
                uint32_t Bv[4];
                ldsmx4t(Bv, s2u(&Xs[(ks*16 + (lane&7) + ((lane>>3)&1)*8)*LDH2 + n + ((lane>>4)&1)*8]));
                mma_bf16(acc[0], A8[ks], Bv);
                mma_bf16(acc[1], A8[ks], Bv+2);
            }
            #pragma unroll
            for(int nh=0; nh<2; ++nh){
                int cc = n + nh*8 + ac;
                float2 x0  = *(const float2*)(xb + (size_t)r0*N_ + cc);
                float2 x1v = *(const float2*)(xb + (size_t)(r0+8)*N_ + cc);
                float y00 = x0.x  + acc[nh][0] + pb0;
                float y01 = x0.y  + acc[nh][1] + pb0;
                float y10 = x1v.x + acc[nh][2] + pb1;
                float y11 = x1v.y + acc[nh][3] + pb1;
                float2 w0 = *(const float2*)(ln1w + (size_t)r0*N_ + n0 + cc);
                float2 w1 = *(const float2*)(ln1w + (size_t)(r0+8)*N_ + n0 + cc);
                float2 g0 = *(const float2*)(ln1b + (size_t)r0*N_ + n0 + cc);
                float2 g1 = *(const float2*)(ln1b + (size_t)(r0+8)*N_ + n0 + cc);
                xv[t][nh][0] = (y00-mu1)*rs1*w0.x + g0.x;
                xv[t][nh][1] = (y01-mu1)*rs1*w0.y + g0.y;
                xv[t][nh][2] = (y10-mu1)*rs1*w1.x + g1.x;
                xv[t][nh][3] = (y11-mu1)*rs1*w1.y + g1.y;
            }
        }
    }
    __syncthreads();
    // ---- phase B: store x1 (fp16 residual + bf16 mma input)
    #pragma unroll
    for(int t=0;t<2;++t){
        int n = nA + t*32;
        #pragma unroll
        for(int nh=0; nh<2; ++nh){
            int cc = n + nh*8 + ac;
            *(__half2*)&X1h[r0*LDXH + cc]     = __floats2half2_rn(xv[t][nh][0], xv[t][nh][1]);
            *(__half2*)&X1h[(r0+8)*LDXH + cc] = __floats2half2_rn(xv[t][nh][2], xv[t][nh][3]);
            *(__nv_bfloat162*)&Xs[r0*LDH2 + cc]     = __floats2bfloat162_rn(xv[t][nh][0], xv[t][nh][1]);
            *(__nv_bfloat162*)&Xs[(r0+8)*LDH2 + cc] = __floats2bfloat162_rn(xv[t][nh][2], xv[t][nh][3]);
        }
    }
    __syncthreads();
    // ---- GEMM1: hid = gelu(W1 x1 + b1): 16 warps x 2 groups of 16 rows
    #pragma unroll
    for(int g=0; g<2; ++g){
        int ch0 = warp*16 + g*256;
        uint32_t Wf[8][4];
        const __nv_bfloat16* w1p = g_W1 + (size_t)ch0*C_;
        #pragma unroll
        for(int ks=0;ks<8;++ks){
            const __nv_bfloat16* wp = w1p + ks*16;
            Wf[ks][0] = *(const uint32_t*)(wp + (size_t)(ar  )*C_ + ac);
            Wf[ks][1] = *(const uint32_t*)(wp + (size_t)(ar+8)*C_ + ac);
            Wf[ks][2] = *(const uint32_t*)(wp + (size_t)(ar  )*C_ + ac + 8);
            Wf[ks][3] = *(const uint32_t*)(wp + (size_t)(ar+8)*C_ + ac + 8);
        }
        float bb0 = b1[ch0 + ar], bb1 = b1[ch0 + ar + 8];
        int hr = ch0 + ar;
        #pragma unroll
        for(int ns=0; ns<4; ++ns){
            float acc[2][4] = {};
            #pragma unroll
            for(int ks=0;ks<8;++ks){
                uint32_t Bv[4];
                ldsmx4t(Bv, s2u(&Xs[(ks*16 + (lane&7) + ((lane>>3)&1)*8)*LDH2 + ns*16 + ((lane>>4)&1)*8]));
                mma_bf16(acc[0], Wf[ks], Bv);
                mma_bf16(acc[1], Wf[ks], Bv+2);
            }
            #pragma unroll
            for(int nh=0; nh<2; ++nh){
                int cc = ns*16 + nh*8 + ac;
                *(__nv_bfloat162*)&Hs[hr*LDH2 + cc] =
                    __floats2bfloat162_rn(gelu_f(acc[nh][0]+bb0), gelu_f(acc[nh][1]+bb0));
                *(__nv_bfloat162*)&Hs[(hr+8)*LDH2 + cc] =
                    __floats2bfloat162_rn(gelu_f(acc[nh][2]+bb1), gelu_f(acc[nh][3]+bb1));
            }
        }
    }
    // ---- GEMM2: z = W2 * hid; warps 8m x 2n (16m x 32n tiles), 64-k chunks
    float zacc[2][2][4];
    #pragma unroll
    for(int a=0;a<2;++a)
        #pragma unroll
        for(int c=0;c<2;++c){ zacc[a][c][0]=0.f; zacc[a][c][1]=0.f;
                              zacc[a][c][2]=0.f; zacc[a][c][3]=0.f; }
    int m0b = (warp&7)*16, nb2 = (warp>>3)*32;
    for(int c0=0; c0<MLP_; c0+=64){
        __syncthreads();
        #pragma unroll
        for(int m=0;m<2;++m){
            int idx = tid + m*512;
            int r = idx>>3, u = idx&7;
            *(uint4*)&W2s[r*LDH2 + u*8] = *(const uint4*)&g_W2[(size_t)r*MLP_ + c0 + u*8];
        }
        __syncthreads();
        #pragma unroll
        for(int ks2=0; ks2<4; ++ks2){
            uint32_t Af[4];
            ldsmx4(Af, s2u(&W2s[(m0b + (lane&15))*LDH2 + ks2*16 + ((lane>>4)&1)*8]));
            #pragma unroll
            for(int nt=0; nt<2; ++nt){
                uint32_t Bv[4];
                ldsmx4t(Bv, s2u(&Hs[(c0 + ks2*16 + (lane&7) + ((lane>>3)&1)*8)*LDH2 + nb2 + nt*16 + ((lane>>4)&1)*8]));
                mma_bf16(zacc[nt][0], Af, Bv);
                mma_bf16(zacc[nt][1], Af, Bv+2);
            }
        }
    }
    // ---- epilogue: z = x1 + zacc + b2 (fp32 stats, fp16 store) ----
    __half* zb = g_z + (size_t)b*NEL + n0;
    int rz = m0b + ar;
    float bz0 = b2[rz], bz1 = b2[rz+8];
    float ls = 0.f, lq = 0.f;
    #pragma unroll
    for(int nt=0; nt<2; ++nt){
        #pragma unroll
        for(int nh=0; nh<2; ++nh){
            int cc = nb2 + nt*16 + nh*8 + ac;
            float2 xa = __half22float2(*(const __half2*)&X1h[rz*LDXH + cc]);
            float2 xc = __half22float2(*(const __half2*)&X1h[(rz+8)*LDXH + cc]);
            float z00 = xa.x + zacc[nt][nh][0] + bz0;
            float z01 = xa.y + zacc[nt][nh][1] + bz0;
            float z10 = xc.x + zacc[nt][nh][2] + bz1;
            float z11 = xc.y + zacc[nt][nh][3] + bz1;
            *(__half2*)(zb + (size_t)rz*N_ + cc)     = __floats2half2_rn(z00, z01);
            *(__half2*)(zb + (size_t)(rz+8)*N_ + cc) = __floats2half2_rn(z10, z11);
            ls += z00+z01+z10+z11;
            lq += z00*z00 + z01*z01 + z10*z10 + z11*z11;
        }
    }
    #pragma unroll
    for(int o=16;o>0;o>>=1){ ls += __shfl_xor_sync(0xffffffffu, ls, o);
                             lq += __shfl_xor_sync(0xffffffffu, lq, o); }
    if(lane==0){ atomicAdd(&g_stats[2][b], ls); atomicAdd(&g_stats[3][b], lq); }
}

// ---------------- K8: out = LN2(z), stats finalized inline -----------------
__global__ void __launch_bounds__(256) k_out(const float* __restrict__ w,
                                             const float* __restrict__ bb,
                                             float* __restrict__ out){
    float mu[B_], rs[B_];
    #pragma unroll
    for(int b=0;b<B_;++b){
        float s = g_stats[2][b], q = g_stats[3][b];
        mu[b] = s / (float)NEL;
        rs[b] = rsqrtf(q / (float)NEL - mu[b]*mu[b] + EPS_);
    }
    size_t nv = (size_t)NEL/4;
    size_t st = (size_t)gridDim.x*blockDim.x;
    for(size_t v = (size_t)blockIdx.x*blockDim.x + threadIdx.x; v < nv; v += st){
        size_t t = v*4;
        float4 wv = *(const float4*)(w + t);
        float4 bv = *(const float4*)(bb + t);
        #pragma unroll
        for(int b=0;b<B_;++b){
            const __half2* zp = (const __half2*)(g_z + (size_t)b*NEL + t);
            float2 zl = __half22float2(zp[0]);
            float2 zh = __half22float2(zp[1]);
            float4 o;
            o.x = (zl.x-mu[b])*rs[b]*wv.x + bv.x;
            o.y = (zl.y-mu[b])*rs[b]*wv.y + bv.y;
            o.z = (zh.x-mu[b])*rs[b]*wv.z + bv.z;
            o.w = (zh.y-mu[b])*rs[b]*wv.w + bv.w;
            *(float4*)(out + (size_t)b*NEL + t) = o;
        }
    }
}

// ---------------- launch ----------------------------------------------------
extern "C" void kernel_launch(void* const* d_in, const int* in_sizes, int n_in,
                              void* d_out, int out_size){
    const float* x      = (const float*)d_in[0];
    const float* qkv_w  = (const float*)d_in[1];
    const float* proj_w = (const float*)d_in[2];
    const float* proj_b = (const float*)d_in[3];
    const float* ln1w   = (const float*)d_in[4];
    const float* ln1b   = (const float*)d_in[5];
    const float* ln2w   = (const float*)d_in[6];
    const float* ln2b   = (const float*)d_in[7];
    const float* w1     = (const float*)d_in[8];
    const float* b1     = (const float*)d_in[9];
    const float* w2     = (const float*)d_in[10];
    const float* b2     = (const float*)d_in[11];
    float* out = (float*)d_out;

    const int SM_A  = (16384 + 4*16*LDS_ + 256)*4;            // 100608
    const int SM_B  = (2*16384 + 2*16*LDS_ + 128 + 64)*4;     // 148864
    const int SM_AM = 73728 + 17408 + 18432;                  // 109568
    cudaFuncSetAttribute(k_attA, cudaFuncAttributeMaxDynamicSharedMemorySize, SM_A);
    cudaFuncSetAttribute(k_attB, cudaFuncAttributeMaxDynamicSharedMemorySize, SM_B);
    cudaFuncSetAttribute(k_am,   cudaFuncAttributeMaxDynamicSharedMemorySize, SM_AM);

    k_init<<<256, 256>>>(w1, w2);
    k_gram<<<dim3(64, 8), 256>>>(x);
    k_attA<<<dim3(8, 8), 1024, SM_A>>>(qkv_w);
    k_attB<<<dim3(8, 8), 1024, SM_B>>>(proj_w, proj_b);
    k_am<<<dim3(8, 512), 512, SM_AM>>>(x, proj_b, ln1w, ln1b, b1, b2);
    k_out<<<4096, 256>>>(ln2w, ln2b, out);
}